// round 15
// baseline (speedup 1.0000x reference)
#include <cuda_runtime.h>
#include <cuda_fp16.h>
#include <math.h>
#include <stdint.h>
#include <string.h>

// Problem constants
#define BATCH 2
#define SEQ   2048
#define DIM   1024
#define NHEAD 16
#define HDIM  64
#define MROWS (BATCH * SEQ)   // 4096

// ---------------------------------------------------------------------------
// Scratch (no allocations allowed -> __device__ globals)
// ---------------------------------------------------------------------------
__device__ __half g_Wqkv[3072 * 1024];
__device__ __half g_Wo  [1024 * 1024];
__device__ __half g_Wfc [4096 * 1024];
__device__ __half g_Wpr [1024 * 4096];

__device__ __half g_h  [MROWS * DIM];
__device__ __half g_qkv[MROWS * 3 * DIM];
__device__ __half g_att[MROWS * DIM];
__device__ float  g_x1 [MROWS * DIM];
__device__ __half g_h2 [MROWS * DIM];
__device__ __half g_fc [MROWS * 4 * DIM];

// ---------------------------------------------------------------------------
// PTX helpers (family-common only: cp.async, ldmatrix, mma.sync)
// ---------------------------------------------------------------------------
__device__ __forceinline__ uint32_t smem_u32(const void* p) {
    uint32_t a;
    asm("{ .reg .u64 t; cvta.to.shared.u64 t, %1; cvt.u32.u64 %0, t; }"
        : "=r"(a) : "l"(p));
    return a;
}

__device__ __forceinline__ void cp16(uint32_t dst, const void* src) {
    asm volatile("cp.async.cg.shared.global [%0], [%1], 16;"
                 :: "r"(dst), "l"(src));
}
#define CP_COMMIT() asm volatile("cp.async.commit_group;" ::: "memory")
#define CP_WAIT1()  asm volatile("cp.async.wait_group 1;" ::: "memory")
#define CP_WAIT0()  asm volatile("cp.async.wait_group 0;" ::: "memory")

__device__ __forceinline__ void ldsm4(uint32_t* r, uint32_t a) {
    asm volatile("ldmatrix.sync.aligned.m8n8.x4.shared.b16 {%0,%1,%2,%3}, [%4];"
                 : "=r"(r[0]), "=r"(r[1]), "=r"(r[2]), "=r"(r[3]) : "r"(a));
}
__device__ __forceinline__ void ldsm4t(uint32_t* r, uint32_t a) {
    asm volatile("ldmatrix.sync.aligned.m8n8.x4.trans.shared.b16 {%0,%1,%2,%3}, [%4];"
                 : "=r"(r[0]), "=r"(r[1]), "=r"(r[2]), "=r"(r[3]) : "r"(a));
}

__device__ __forceinline__ void mma16816(float* d, const uint32_t* a,
                                         uint32_t b0, uint32_t b1) {
    asm volatile(
        "mma.sync.aligned.m16n8k16.row.col.f32.f16.f16.f32 "
        "{%0,%1,%2,%3}, {%4,%5,%6,%7}, {%8,%9}, {%0,%1,%2,%3};"
        : "+f"(d[0]), "+f"(d[1]), "+f"(d[2]), "+f"(d[3])
        : "r"(a[0]), "r"(a[1]), "r"(a[2]), "r"(a[3]), "r"(b0), "r"(b1));
}

// single-instruction packed fp32->fp16x2 convert (cvt.rn.f16x2.f32)
__device__ __forceinline__ uint32_t pkcvt(float a, float b) {
    __half2 t = __floats2half2_rn(a, b);
    uint32_t r;
    memcpy(&r, &t, 4);
    return r;
}
__device__ __forceinline__ void st_h2(__half* p, float a, float b) {
    *(__half2*)p = __floats2half2_rn(a, b);
}

// ---------------------------------------------------------------------------
// fp16 mma.sync GEMM, single pass, BN=128, 2 CTAs/SM.
// A fp16 [M,K] K-major, B fp16 [N,K] K-major.
// Block tile 128x128, K-chunk 64, 8 warps (4x2), warp tile 32x64.
// 3-stage cp.async, ONE __syncthreads per chunk, loads lead compute.
// EPI=1: res tile prefetched into free smem stages during the last K-chunk.
// EPI: 1 = +bias+res -> fp32; 2 = gelu(+bias) -> fp16; 3 = +bias -> fp16
// ---------------------------------------------------------------------------
#define TS 72                        // smem row stride in fp16 elems (144 bytes)
#define ROWB (TS * 2)                // 144
#define TILE_B128 (128 * ROWB)       // 18432
#define STAGE128  (2 * TILE_B128)    // 36864
#define GEMM128_SMEM (3 * STAGE128)  // 110592
#define RES_ROWB 528                 // res smem row stride (bytes)

template <int EPI>
__global__ __launch_bounds__(256, 2) void gemm128(
    const __half* __restrict__ A, const __half* __restrict__ B,
    const float* __restrict__ bias, const float* __restrict__ res,
    float* __restrict__ Co, __half* __restrict__ Ch,
    int M, int N, int K)
{
    extern __shared__ char sm_raw[];
    uint32_t sb = smem_u32(sm_raw);

    int tid  = threadIdx.x;
    int w    = tid >> 5;
    int lane = tid & 31;
    int wm   = w >> 1;               // 0..3  (32-row group)
    int wn   = w & 1;                // 0..1  (64-col group)
    int n0   = blockIdx.x * 128;
    int m0   = blockIdx.y * 128;

    const __half* srcA = A + (size_t)m0 * K;
    const __half* srcB = B + (size_t)n0 * K;

    float acc[2][8][4];
    #pragma unroll
    for (int i = 0; i < 2; i++)
        #pragma unroll
        for (int j = 0; j < 8; j++)
            #pragma unroll
            for (int q = 0; q < 4; q++) acc[i][j][q] = 0.0f;

    int nch = K >> 6;                // K/64
    bool pre = (EPI == 1) && (((nch - 1) % 3) == 0);

    auto load_stage = [&](int c, int s) {
        int k0 = c << 6;
        uint32_t stg = sb + s * STAGE128;
        #pragma unroll
        for (int it = 0; it < 8; it++) {
            int idx = it * 256 + tid;          // 0..2047
            int mat   = idx >> 10;             // 0: A, 1: B
            int rem   = idx & 1023;
            int row   = rem >> 3;
            int chunk = rem & 7;
            const __half* src = (mat ? srcB : srcA) + (size_t)row * K + k0 + chunk * 8;
            uint32_t dst = stg + mat * TILE_B128
                         + (uint32_t)(row * ROWB + chunk * 16);
            cp16(dst, src);
        }
        CP_COMMIT();
    };

    load_stage(0, 0);
    if (nch > 1) load_stage(1, 1);

    int arow = wm * 32 + (lane & 15);
    uint32_t a_off = (uint32_t)(arow * ROWB) + (uint32_t)((lane >> 4) * 16);
    int bmat = lane >> 3;
    int b_h  = bmat & 1;
    int b_j  = bmat >> 1;
    uint32_t b_off = (uint32_t)((wn * 64 + b_j * 8 + (lane & 7)) * ROWB)
                   + (uint32_t)(b_h * 16);

    for (int c = 0; c < nch; c++) {
        int s = c % 3;
        if (c + 1 < nch) { CP_WAIT1(); } else { CP_WAIT0(); }
        __syncthreads();
        if (c + 2 < nch) load_stage(c + 2, (c + 2) % 3);
        else if (pre && c == nch - 1) {
            const float* rbase = res + (size_t)m0 * N + n0;
            uint32_t rdst = sb + STAGE128;
            #pragma unroll
            for (int it = 0; it < 16; it++) {
                int idx = it * 256 + tid;      // 0..4095
                int row = idx >> 5;
                int ch  = idx & 31;
                cp16(rdst + (uint32_t)(row * RES_ROWB + ch * 16),
                     rbase + (size_t)row * N + ch * 4);
            }
            CP_COMMIT();
        }

        uint32_t stg = sb + s * STAGE128;
        uint32_t pA = stg;
        uint32_t pB = stg + TILE_B128;

        #pragma unroll
        for (int kk = 0; kk < 64; kk += 16) {
            uint32_t kb = (uint32_t)kk * 2;
            uint32_t ah[2][4];
            #pragma unroll
            for (int i = 0; i < 2; i++)
                ldsm4(ah[i], pA + a_off + kb + (uint32_t)(i * 16 * ROWB));
            #pragma unroll
            for (int g = 0; g < 4; g++) {
                uint32_t boff = b_off + (uint32_t)(g * 16 * ROWB) + kb;
                uint32_t bh[4];
                ldsm4(bh, pB + boff);
                int j0 = 2 * g, j1 = 2 * g + 1;
                #pragma unroll
                for (int i = 0; i < 2; i++) {
                    mma16816(acc[i][j0], ah[i], bh[0], bh[1]);
                    mma16816(acc[i][j1], ah[i], bh[2], bh[3]);
                }
            }
        }
    }

    if (pre) { CP_WAIT0(); __syncthreads(); }

    // Epilogue
    int r0 = m0 + wm * 32 + (lane >> 2);
    int c0 = n0 + wn * 64 + (lane & 3) * 2;
    int lr0 = wm * 32 + (lane >> 2);
    int lc0 = wn * 64 + (lane & 3) * 2;
    #pragma unroll
    for (int i = 0; i < 2; i++) {
        int row = r0 + i * 16;
        #pragma unroll
        for (int j = 0; j < 8; j++) {
            int col = c0 + j * 8;
            float b0 = bias[col], b1 = bias[col + 1];
            float v0 = acc[i][j][0] + b0;
            float v1 = acc[i][j][1] + b1;
            float v2 = acc[i][j][2] + b0;
            float v3 = acc[i][j][3] + b1;
            if (EPI == 1) {
                float2 r0v, r1v;
                if (pre) {
                    int lr = lr0 + i * 16;
                    int lc = lc0 + j * 8;
                    r0v = *(const float2*)(sm_raw + STAGE128 + lr * RES_ROWB + lc * 4);
                    r1v = *(const float2*)(sm_raw + STAGE128 + (lr + 8) * RES_ROWB + lc * 4);
                } else {
                    r0v = *(const float2*)(res + (size_t)row * N + col);
                    r1v = *(const float2*)(res + (size_t)(row + 8) * N + col);
                }
                v0 += r0v.x; v1 += r0v.y;
                v2 += r1v.x; v3 += r1v.y;
                *(float2*)(Co + (size_t)row * N + col) = make_float2(v0, v1);
                *(float2*)(Co + (size_t)(row + 8) * N + col) = make_float2(v2, v3);
            } else {
                if (EPI == 2) {
                    v0 = 0.5f * v0 * (1.0f + erff(v0 * 0.70710678118654752f));
                    v1 = 0.5f * v1 * (1.0f + erff(v1 * 0.70710678118654752f));
                    v2 = 0.5f * v2 * (1.0f + erff(v2 * 0.70710678118654752f));
                    v3 = 0.5f * v3 * (1.0f + erff(v3 * 0.70710678118654752f));
                }
                st_h2(Ch + (size_t)row * N + col, v0, v1);
                st_h2(Ch + (size_t)(row + 8) * N + col, v2, v3);
            }
        }
    }
}

// ---------------------------------------------------------------------------
// Fused prep: 4 weight transposes + LN1, one launch.
// ---------------------------------------------------------------------------
__global__ __launch_bounds__(256) void prep_all(
    const float* __restrict__ Wq, const float* __restrict__ Wo,
    const float* __restrict__ Wf, const float* __restrict__ Wp,
    __half* __restrict__ Tq, __half* __restrict__ To,
    __half* __restrict__ Tf, __half* __restrict__ Tp,
    const float* __restrict__ x, const float* __restrict__ g1,
    const float* __restrict__ beta1, __half* __restrict__ yln)
{
    int bid = blockIdx.x;
    if (bid < 12288) {
        const float* W; __half* T; int K, N, r;
        if (bid < 3072)      { W = Wq; T = Tq; K = 1024; N = 3072; r = bid; }
        else if (bid < 4096) { W = Wo; T = To; K = 1024; N = 1024; r = bid - 3072; }
        else if (bid < 8192) { W = Wf; T = Tf; K = 1024; N = 4096; r = bid - 4096; }
        else                 { W = Wp; T = Tp; K = 4096; N = 1024; r = bid - 8192; }
        int nbx = N >> 5;
        int n0 = (r % nbx) * 32, k0 = (r / nbx) * 32;

        __shared__ float t[32][33];
        int tx = threadIdx.x & 31, ty = threadIdx.x >> 5;
        #pragma unroll
        for (int i = 0; i < 4; i++) {
            int kr = ty * 4 + i;
            t[kr][tx] = W[(size_t)(k0 + kr) * N + n0 + tx];
        }
        __syncthreads();
        #pragma unroll
        for (int i = 0; i < 4; i++) {
            int nr = ty * 4 + i;
            T[(size_t)(n0 + nr) * K + k0 + tx] = __float2half(t[tx][nr]);
        }
    } else {
        __shared__ float sh[16];
        int row = bid - 12288;
        int t = threadIdx.x;
        const float4* xr = (const float4*)(x + (size_t)row * DIM);
        float4 v = xr[t];
        float s  = v.x + v.y + v.z + v.w;
        float s2 = v.x*v.x + v.y*v.y + v.z*v.z + v.w*v.w;
        #pragma unroll
        for (int o = 16; o > 0; o >>= 1) {
            s  += __shfl_xor_sync(0xffffffffu, s,  o);
            s2 += __shfl_xor_sync(0xffffffffu, s2, o);
        }
        if ((t & 31) == 0) { sh[t >> 5] = s; sh[8 + (t >> 5)] = s2; }
        __syncthreads();
        if (t < 32) {
            float a  = (t < 8) ? sh[t]     : 0.0f;
            float a2 = (t < 8) ? sh[8 + t] : 0.0f;
            #pragma unroll
            for (int o = 4; o > 0; o >>= 1) {
                a  += __shfl_xor_sync(0xffffffffu, a,  o);
                a2 += __shfl_xor_sync(0xffffffffu, a2, o);
            }
            if (t == 0) { sh[0] = a; sh[1] = a2; }
        }
        __syncthreads();
        float mean = sh[0] * (1.0f / DIM);
        float var  = sh[1] * (1.0f / DIM) - mean * mean;
        float rstd = rsqrtf(var + 1e-5f);
        float4 gg = ((const float4*)g1)[t];
        float4 bb = ((const float4*)beta1)[t];
        float o0 = (v.x - mean) * rstd * gg.x + bb.x;
        float o1 = (v.y - mean) * rstd * gg.y + bb.y;
        float o2 = (v.z - mean) * rstd * gg.z + bb.z;
        float o3 = (v.w - mean) * rstd * gg.w + bb.w;
        size_t o = (size_t)row * DIM + t * 4;
        st_h2(yln + o, o0, o1);
        st_h2(yln + o + 2, o2, o3);
    }
}

// ---------------------------------------------------------------------------
// LayerNorm -> fp16 output. One block per row, 256 threads, float4. (LN2)
// ---------------------------------------------------------------------------
__global__ __launch_bounds__(256) void ln_kernel(
    const float* __restrict__ x, const float* __restrict__ g,
    const float* __restrict__ b, __half* __restrict__ y)
{
    __shared__ float sh[16];
    int row = blockIdx.x;
    int t = threadIdx.x;
    const float4* xr = (const float4*)(x + (size_t)row * DIM);
    float4 v = xr[t];
    float s  = v.x + v.y + v.z + v.w;
    float s2 = v.x*v.x + v.y*v.y + v.z*v.z + v.w*v.w;
    #pragma unroll
    for (int o = 16; o > 0; o >>= 1) {
        s  += __shfl_xor_sync(0xffffffffu, s,  o);
        s2 += __shfl_xor_sync(0xffffffffu, s2, o);
    }
    if ((t & 31) == 0) { sh[t >> 5] = s; sh[8 + (t >> 5)] = s2; }
    __syncthreads();
    if (t < 32) {
        float a  = (t < 8) ? sh[t]     : 0.0f;
        float a2 = (t < 8) ? sh[8 + t] : 0.0f;
        #pragma unroll
        for (int o = 4; o > 0; o >>= 1) {
            a  += __shfl_xor_sync(0xffffffffu, a,  o);
            a2 += __shfl_xor_sync(0xffffffffu, a2, o);
        }
        if (t == 0) { sh[0] = a; sh[1] = a2; }
    }
    __syncthreads();
    float mean = sh[0] * (1.0f / DIM);
    float var  = sh[1] * (1.0f / DIM) - mean * mean;
    float rstd = rsqrtf(var + 1e-5f);
    float4 gg = ((const float4*)g)[t];
    float4 bb = ((const float4*)b)[t];
    float o0 = (v.x - mean) * rstd * gg.x + bb.x;
    float o1 = (v.y - mean) * rstd * gg.y + bb.y;
    float o2 = (v.z - mean) * rstd * gg.z + bb.z;
    float o3 = (v.w - mean) * rstd * gg.w + bb.w;
    size_t o = (size_t)row * DIM + t * 4;
    st_h2(y + o, o0, o1);
    st_h2(y + o + 2, o2, o3);
}

// ---------------------------------------------------------------------------
// Flash attention on fp16 mma.sync, single-precision-pass.
// CTA: 128 queries x one (b,h). 8 warps, 16 q-rows each.
// KV staged in 128-row blocks (double-buffered), two 64-row halves per iter.
// Base-2 softmax; alpha-rescale skipped (bit-exact) when running max unchanged.
// ---------------------------------------------------------------------------
#define AT_ROWB   144
#define AT_TILE   (128 * AT_ROWB)    // 18432 per matrix (K or V), 128 rows
#define AT_STAGE  (2 * AT_TILE)      // 36864 (K, V)
#define ATTN_SMEM (2 * AT_STAGE)     // 73728
#define SCL2 0.18033688011112042f    // 0.125 * log2(e)

__global__ __launch_bounds__(256) void attn_mma(
    const __half* __restrict__ qkv,
    __half* __restrict__ oout)
{
    extern __shared__ char sm_raw[];
    uint32_t sb = smem_u32(sm_raw);

    int tid  = threadIdx.x;
    int w    = tid >> 5;
    int lane = tid & 31;
    int qb   = (int)(gridDim.x - 1 - blockIdx.x);   // long CTAs first
    int bhid = blockIdx.y;
    int b    = bhid >> 4;
    int h    = bhid & 15;
    int q0   = qb * 128;
    const int D3 = 3 * DIM;
    size_t rowbase = (size_t)(b * SEQ) * D3 + h * 64;

    const __half* kv_srcs[2] = { qkv + rowbase + DIM, qkv + rowbase + 2 * DIM };

    auto load_kv = [&](int blk, int s) {
        #pragma unroll
        for (int it = 0; it < 8; it++) {
            int idx = it * 256 + tid;
            int mat = idx >> 10;
            int rem = idx & 1023;
            int row = rem >> 3;
            int c   = rem & 7;
            const __half* src =
                kv_srcs[mat] + (size_t)(blk * 128 + row) * D3 + c * 8;
            cp16(sb + s * AT_STAGE + mat * AT_TILE + row * AT_ROWB + c * 16, src);
        }
        CP_COMMIT();
    };

    // ---- Q into stage-1 K area + KV block 0 into stage-0, one group ----
    {
        uint32_t qbase_s = sb + AT_STAGE;
        #pragma unroll
        for (int it = 0; it < 4; it++) {
            int idx = it * 256 + tid;
            int row = idx >> 3;
            int c   = idx & 7;
            const __half* src = qkv + rowbase + (size_t)(q0 + row) * D3 + c * 8;
            cp16(qbase_s + (uint32_t)(row * AT_ROWB + c * 16), src);
        }
        #pragma unroll
        for (int it = 0; it < 8; it++) {
            int idx = it * 256 + tid;
            int mat = idx >> 10;
            int rem = idx & 1023;
            int row = rem >> 3;
            int c   = rem & 7;
            const __half* src = kv_srcs[mat] + (size_t)(row) * D3 + c * 8;
            cp16(sb + mat * AT_TILE + row * AT_ROWB + c * 16, src);
        }
        CP_COMMIT();
    }
    CP_WAIT0();
    __syncthreads();

    uint32_t qf[4][4];
    {
        int row = w * 16 + (lane & 15);
        uint32_t boff = (uint32_t)(row * AT_ROWB) + (uint32_t)((lane >> 4) * 16);
        #pragma unroll
        for (int kk = 0; kk < 4; kk++)
            ldsm4(qf[kk], sb + AT_STAGE + boff + kk * 32);
    }
    __syncthreads();

    float m2[2] = { -1e30f, -1e30f };
    float l2[2] = { 0.0f, 0.0f };
    float oacc[8][4];
    #pragma unroll
    for (int j = 0; j < 8; j++)
        #pragma unroll
        for (int q = 0; q < 4; q++) oacc[j][q] = 0.0f;

    int nblk = qb + 1;
    int qrow0 = q0 + w * 16 + (lane >> 2);

    for (int blk = 0; blk < nblk; blk++) {
        int s = blk & 1;
        if (blk + 1 < nblk) { load_kv(blk + 1, s ^ 1); CP_WAIT1(); }
        else                { CP_WAIT0(); }
        __syncthreads();

        #pragma unroll
        for (int half = 0; half < 2; half++) {
            int kvbase = blk * 128 + half * 64;
            bool active = (kvbase <= q0 + w * 16 + 15);
            if (!active) continue;

            uint32_t kb_s = sb + s * AT_STAGE + (uint32_t)(half * 64 * AT_ROWB);
            uint32_t vb_s = kb_s + AT_TILE;

            float sacc[8][4];
            #pragma unroll
            for (int j = 0; j < 8; j++)
                #pragma unroll
                for (int q = 0; q < 4; q++) sacc[j][q] = 0.0f;

            int bm   = lane >> 3;
            int bkh  = bm & 1;
            int bjj  = bm >> 1;
            int brow = (lane & 7) + bjj * 8;
            #pragma unroll
            for (int jp = 0; jp < 4; jp++) {
                #pragma unroll
                for (int kk = 0; kk < 4; kk++) {
                    uint32_t off = (uint32_t)((jp * 16 + brow) * AT_ROWB)
                                 + (uint32_t)((bkh * 8 + kk * 16) * 2);
                    uint32_t khr[4];
                    ldsm4(khr, kb_s + off);
                    mma16816(sacc[2 * jp],     qf[kk], khr[0], khr[1]);
                    mma16816(sacc[2 * jp + 1], qf[kk], khr[2], khr[3]);
                }
            }

            bool needmask = (kvbase + 63 > q0 + w * 16);
            #pragma unroll
            for (int hh = 0; hh < 2; hh++) {
                int qrow = qrow0 + hh * 8;
                #pragma unroll
                for (int j = 0; j < 8; j++) {
                    #pragma unroll
                    for (int c = 0; c < 2; c++) {
                        float v = sacc[j][2 * hh + c] * SCL2;
                        if (needmask) {
                            int kv = kvbase + j * 8 + (lane & 3) * 2 + c;
                            if (kv > qrow) v = -1e30f;
                        }
                        sacc[j][2 * hh + c] = v;
                    }
                }
                float mx = -1e30f;
                #pragma unroll
                for (int j = 0; j < 8; j++)
                    mx = fmaxf(mx, fmaxf(sacc[j][2 * hh], sacc[j][2 * hh + 1]));
                mx = fmaxf(mx, __shfl_xor_sync(0xffffffffu, mx, 1));
                mx = fmaxf(mx, __shfl_xor_sync(0xffffffffu, mx, 2));
                float mold = m2[hh];
                float mn = fmaxf(mold, mx);
                float sum = 0.0f;
                #pragma unroll
                for (int j = 0; j < 8; j++) {
                    float p0 = exp2f(sacc[j][2 * hh]     - mn);
                    float p1 = exp2f(sacc[j][2 * hh + 1] - mn);
                    sacc[j][2 * hh]     = p0;
                    sacc[j][2 * hh + 1] = p1;
                    sum += p0 + p1;
                }
                sum += __shfl_xor_sync(0xffffffffu, sum, 1);
                sum += __shfl_xor_sync(0xffffffffu, sum, 2);
                if (mn > mold) {
                    float alpha = exp2f(mold - mn);
                    m2[hh] = mn;
                    l2[hh] = l2[hh] * alpha + sum;
                    #pragma unroll
                    for (int j = 0; j < 8; j++) {
                        oacc[j][2 * hh]     *= alpha;
                        oacc[j][2 * hh + 1] *= alpha;
                    }
                } else {
                    l2[hh] += sum;
                }
            }

            uint32_t pah[4][4];
            #pragma unroll
            for (int kk = 0; kk < 4; kk++) {
                #pragma unroll
                for (int t = 0; t < 4; t++) {
                    int j  = 2 * kk + (t >> 1);
                    int ci = (t & 1) * 2;
                    pah[kk][t] = pkcvt(sacc[j][ci], sacc[j][ci + 1]);
                }
            }

            int r   = lane & 7;
            int mm  = lane >> 3;
            #pragma unroll
            for (int jp = 0; jp < 4; jp++) {
                #pragma unroll
                for (int kk = 0; kk < 4; kk++) {
                    uint32_t off = (uint32_t)((kk * 16 + r + (mm & 1) * 8) * AT_ROWB)
                                 + (uint32_t)((jp * 16 + (mm >> 1) * 8) * 2);
                    uint32_t vhr[4];
                    ldsm4t(vhr, vb_s + off);
                    mma16816(oacc[2 * jp],     pah[kk], vhr[0], vhr[1]);
                    mma16816(oacc[2 * jp + 1], pah[kk], vhr[2], vhr[3]);
                }
            }
        }
        __syncthreads();
    }

    float inv0 = 1.0f / l2[0];
    float inv1 = 1.0f / l2[1];
    size_t obase = (size_t)(b * SEQ) * DIM + h * 64;
    int row1 = q0 + w * 16 + (lane >> 2);
    int colb = (lane & 3) * 2;
    #pragma unroll
    for (int j = 0; j < 8; j++) {
        int col = j * 8 + colb;
        st_h2(oout + obase + (size_t)row1 * DIM + col,
              oacc[j][0] * inv0, oacc[j][1] * inv0);
        st_h2(oout + obase + (size_t)(row1 + 8) * DIM + col,
              oacc[j][2] * inv1, oacc[j][3] * inv1);
    }
}

// ---------------------------------------------------------------------------
// Launch
// ---------------------------------------------------------------------------
extern "C" void kernel_launch(void* const* d_in, const int* in_sizes, int n_in,
                              void* d_out, int out_size)
{
    const float* x      = (const float*)d_in[0];
    const float* W_qkv  = (const float*)d_in[1];
    const float* b_qkv  = (const float*)d_in[2];
    const float* W_o    = (const float*)d_in[3];
    const float* b_o    = (const float*)d_in[4];
    const float* W_fc   = (const float*)d_in[5];
    const float* b_fc   = (const float*)d_in[6];
    const float* W_pr   = (const float*)d_in[7];
    const float* b_pr   = (const float*)d_in[8];
    const float* g1     = (const float*)d_in[9];
    const float* beta1  = (const float*)d_in[10];
    const float* g2     = (const float*)d_in[11];
    const float* beta2  = (const float*)d_in[12];
    float* out = (float*)d_out;

    __half *pWq, *pWo, *pWf, *pWp;
    __half *ph, *pq, *pat, *ph2, *pfc;
    float *px1;
    cudaGetSymbolAddress((void**)&pWq,  g_Wqkv);
    cudaGetSymbolAddress((void**)&pWo,  g_Wo);
    cudaGetSymbolAddress((void**)&pWf,  g_Wfc);
    cudaGetSymbolAddress((void**)&pWp,  g_Wpr);
    cudaGetSymbolAddress((void**)&ph,   g_h);
    cudaGetSymbolAddress((void**)&pq,   g_qkv);
    cudaGetSymbolAddress((void**)&pat,  g_att);
    cudaGetSymbolAddress((void**)&px1,  g_x1);
    cudaGetSymbolAddress((void**)&ph2,  g_h2);
    cudaGetSymbolAddress((void**)&pfc,  g_fc);

    cudaFuncSetAttribute(attn_mma,
                         cudaFuncAttributeMaxDynamicSharedMemorySize, ATTN_SMEM);
    cudaFuncSetAttribute(gemm128<1>,
                         cudaFuncAttributeMaxDynamicSharedMemorySize, GEMM128_SMEM);
    cudaFuncSetAttribute(gemm128<2>,
                         cudaFuncAttributeMaxDynamicSharedMemorySize, GEMM128_SMEM);
    cudaFuncSetAttribute(gemm128<3>,
                         cudaFuncAttributeMaxDynamicSharedMemorySize, GEMM128_SMEM);

    // 0. Fused prep: weight transposes + LN1, one launch
    prep_all<<<16384, 256>>>(W_qkv, W_o, W_fc, W_pr, pWq, pWo, pWf, pWp,
                             x, g1, beta1, ph);
    // 2. QKV projection -> fp16
    gemm128<3><<<dim3(3072 / 128, MROWS / 128), 256, GEMM128_SMEM>>>(
        ph, pWq, b_qkv, nullptr, nullptr, pq, MROWS, 3 * DIM, DIM);
    // 3. Attention (tensor-core flash) -> att fp16
    attn_mma<<<dim3(SEQ / 128, BATCH * NHEAD), 256, ATTN_SMEM>>>(pq, pat);
    // 4. Output projection + residual -> x1 (fp32)
    gemm128<1><<<dim3(DIM / 128, MROWS / 128), 256, GEMM128_SMEM>>>(
        pat, pWo, b_o, x, px1, nullptr, MROWS, DIM, DIM);
    // 5. LN2 -> h2 (fp16)
    ln_kernel<<<MROWS, 256>>>(px1, g2, beta2, ph2);
    // 6. FC + GELU -> fc (fp16)
    gemm128<2><<<dim3(4 * DIM / 128, MROWS / 128), 256, GEMM128_SMEM>>>(
        ph2, pWf, b_fc, nullptr, nullptr, pfc, MROWS, 4 * DIM, DIM);
    // 7. Projection + residual -> out (fp32)
    gemm128<1><<<dim3(DIM / 128, MROWS / 128), 256, GEMM128_SMEM>>>(
        pfc, pWp, b_pr, px1, out, nullptr, MROWS, DIM, 4 * DIM);
}

// round 16
// speedup vs baseline: 1.0171x; 1.0171x over previous
#include <cuda_runtime.h>
#include <cuda_fp16.h>
#include <math.h>
#include <stdint.h>
#include <string.h>

// Problem constants
#define BATCH 2
#define SEQ   2048
#define DIM   1024
#define NHEAD 16
#define HDIM  64
#define MROWS (BATCH * SEQ)   // 4096

// ---------------------------------------------------------------------------
// Scratch (no allocations allowed -> __device__ globals)
// ---------------------------------------------------------------------------
__device__ __half g_Wqkv[3072 * 1024];
__device__ __half g_Wo  [1024 * 1024];
__device__ __half g_Wfc [4096 * 1024];
__device__ __half g_Wpr [1024 * 4096];

__device__ __half g_h  [MROWS * DIM];
__device__ __half g_qkv[MROWS * 3 * DIM];
__device__ __half g_att[MROWS * DIM];
__device__ float  g_x1 [MROWS * DIM];
__device__ __half g_h2 [MROWS * DIM];
__device__ __half g_fc [MROWS * 4 * DIM];

// ---------------------------------------------------------------------------
// PTX helpers (family-common only: cp.async, ldmatrix, mma.sync)
// ---------------------------------------------------------------------------
__device__ __forceinline__ uint32_t smem_u32(const void* p) {
    uint32_t a;
    asm("{ .reg .u64 t; cvta.to.shared.u64 t, %1; cvt.u32.u64 %0, t; }"
        : "=r"(a) : "l"(p));
    return a;
}

__device__ __forceinline__ void cp16(uint32_t dst, const void* src) {
    asm volatile("cp.async.cg.shared.global [%0], [%1], 16;"
                 :: "r"(dst), "l"(src));
}
#define CP_COMMIT() asm volatile("cp.async.commit_group;" ::: "memory")
#define CP_WAIT1()  asm volatile("cp.async.wait_group 1;" ::: "memory")
#define CP_WAIT0()  asm volatile("cp.async.wait_group 0;" ::: "memory")

__device__ __forceinline__ void ldsm4(uint32_t* r, uint32_t a) {
    asm volatile("ldmatrix.sync.aligned.m8n8.x4.shared.b16 {%0,%1,%2,%3}, [%4];"
                 : "=r"(r[0]), "=r"(r[1]), "=r"(r[2]), "=r"(r[3]) : "r"(a));
}
__device__ __forceinline__ void ldsm4t(uint32_t* r, uint32_t a) {
    asm volatile("ldmatrix.sync.aligned.m8n8.x4.trans.shared.b16 {%0,%1,%2,%3}, [%4];"
                 : "=r"(r[0]), "=r"(r[1]), "=r"(r[2]), "=r"(r[3]) : "r"(a));
}

__device__ __forceinline__ void mma16816(float* d, const uint32_t* a,
                                         uint32_t b0, uint32_t b1) {
    asm volatile(
        "mma.sync.aligned.m16n8k16.row.col.f32.f16.f16.f32 "
        "{%0,%1,%2,%3}, {%4,%5,%6,%7}, {%8,%9}, {%0,%1,%2,%3};"
        : "+f"(d[0]), "+f"(d[1]), "+f"(d[2]), "+f"(d[3])
        : "r"(a[0]), "r"(a[1]), "r"(a[2]), "r"(a[3]), "r"(b0), "r"(b1));
}

// single-instruction packed fp32->fp16x2 convert (cvt.rn.f16x2.f32)
__device__ __forceinline__ uint32_t pkcvt(float a, float b) {
    __half2 t = __floats2half2_rn(a, b);
    uint32_t r;
    memcpy(&r, &t, 4);
    return r;
}
__device__ __forceinline__ void st_h2(__half* p, float a, float b) {
    *(__half2*)p = __floats2half2_rn(a, b);
}

// ---------------------------------------------------------------------------
// fp16 mma.sync GEMM, single pass, BN=128, 2 CTAs/SM.
// A fp16 [M,K] K-major, B fp16 [N,K] K-major.
// Block tile 128x128, K-chunk 64, 8 warps (4x2), warp tile 32x64.
// 3-stage cp.async, ONE __syncthreads per chunk, loads lead compute.
// EPI=1: res tile prefetched into free smem stages during the last K-chunk.
// EPI: 1 = +bias+res -> fp32; 2 = gelu(+bias) -> fp16; 3 = +bias -> fp16
// ---------------------------------------------------------------------------
#define TS 72                        // smem row stride in fp16 elems (144 bytes)
#define ROWB (TS * 2)                // 144
#define TILE_B128 (128 * ROWB)       // 18432
#define STAGE128  (2 * TILE_B128)    // 36864
#define GEMM128_SMEM (3 * STAGE128)  // 110592
#define RES_ROWB 528                 // res smem row stride (bytes)

template <int EPI>
__global__ __launch_bounds__(256, 2) void gemm128(
    const __half* __restrict__ A, const __half* __restrict__ B,
    const float* __restrict__ bias, const float* __restrict__ res,
    float* __restrict__ Co, __half* __restrict__ Ch,
    int M, int N, int K)
{
    extern __shared__ char sm_raw[];
    uint32_t sb = smem_u32(sm_raw);

    int tid  = threadIdx.x;
    int w    = tid >> 5;
    int lane = tid & 31;
    int wm   = w >> 1;               // 0..3  (32-row group)
    int wn   = w & 1;                // 0..1  (64-col group)
    int n0   = blockIdx.x * 128;
    int m0   = blockIdx.y * 128;

    const __half* srcA = A + (size_t)m0 * K;
    const __half* srcB = B + (size_t)n0 * K;

    float acc[2][8][4];
    #pragma unroll
    for (int i = 0; i < 2; i++)
        #pragma unroll
        for (int j = 0; j < 8; j++)
            #pragma unroll
            for (int q = 0; q < 4; q++) acc[i][j][q] = 0.0f;

    int nch = K >> 6;                // K/64
    bool pre = (EPI == 1) && (((nch - 1) % 3) == 0);

    auto load_stage = [&](int c, int s) {
        int k0 = c << 6;
        uint32_t stg = sb + s * STAGE128;
        #pragma unroll
        for (int it = 0; it < 8; it++) {
            int idx = it * 256 + tid;          // 0..2047
            int mat   = idx >> 10;             // 0: A, 1: B
            int rem   = idx & 1023;
            int row   = rem >> 3;
            int chunk = rem & 7;
            const __half* src = (mat ? srcB : srcA) + (size_t)row * K + k0 + chunk * 8;
            uint32_t dst = stg + mat * TILE_B128
                         + (uint32_t)(row * ROWB + chunk * 16);
            cp16(dst, src);
        }
        CP_COMMIT();
    };

    load_stage(0, 0);
    if (nch > 1) load_stage(1, 1);

    int arow = wm * 32 + (lane & 15);
    uint32_t a_off = (uint32_t)(arow * ROWB) + (uint32_t)((lane >> 4) * 16);
    int bmat = lane >> 3;
    int b_h  = bmat & 1;
    int b_j  = bmat >> 1;
    uint32_t b_off = (uint32_t)((wn * 64 + b_j * 8 + (lane & 7)) * ROWB)
                   + (uint32_t)(b_h * 16);

    for (int c = 0; c < nch; c++) {
        int s = c % 3;
        if (c + 1 < nch) { CP_WAIT1(); } else { CP_WAIT0(); }
        __syncthreads();
        if (c + 2 < nch) load_stage(c + 2, (c + 2) % 3);
        else if (pre && c == nch - 1) {
            const float* rbase = res + (size_t)m0 * N + n0;
            uint32_t rdst = sb + STAGE128;
            #pragma unroll
            for (int it = 0; it < 16; it++) {
                int idx = it * 256 + tid;      // 0..4095
                int row = idx >> 5;
                int ch  = idx & 31;
                cp16(rdst + (uint32_t)(row * RES_ROWB + ch * 16),
                     rbase + (size_t)row * N + ch * 4);
            }
            CP_COMMIT();
        }

        uint32_t stg = sb + s * STAGE128;
        uint32_t pA = stg;
        uint32_t pB = stg + TILE_B128;

        #pragma unroll
        for (int kk = 0; kk < 64; kk += 16) {
            uint32_t kb = (uint32_t)kk * 2;
            uint32_t ah[2][4];
            #pragma unroll
            for (int i = 0; i < 2; i++)
                ldsm4(ah[i], pA + a_off + kb + (uint32_t)(i * 16 * ROWB));
            #pragma unroll
            for (int g = 0; g < 4; g++) {
                uint32_t boff = b_off + (uint32_t)(g * 16 * ROWB) + kb;
                uint32_t bh[4];
                ldsm4(bh, pB + boff);
                int j0 = 2 * g, j1 = 2 * g + 1;
                #pragma unroll
                for (int i = 0; i < 2; i++) {
                    mma16816(acc[i][j0], ah[i], bh[0], bh[1]);
                    mma16816(acc[i][j1], ah[i], bh[2], bh[3]);
                }
            }
        }
    }

    if (pre) { CP_WAIT0(); __syncthreads(); }

    // Epilogue
    int r0 = m0 + wm * 32 + (lane >> 2);
    int c0 = n0 + wn * 64 + (lane & 3) * 2;
    int lr0 = wm * 32 + (lane >> 2);
    int lc0 = wn * 64 + (lane & 3) * 2;
    #pragma unroll
    for (int i = 0; i < 2; i++) {
        int row = r0 + i * 16;
        #pragma unroll
        for (int j = 0; j < 8; j++) {
            int col = c0 + j * 8;
            float b0 = bias[col], b1 = bias[col + 1];
            float v0 = acc[i][j][0] + b0;
            float v1 = acc[i][j][1] + b1;
            float v2 = acc[i][j][2] + b0;
            float v3 = acc[i][j][3] + b1;
            if (EPI == 1) {
                float2 r0v, r1v;
                if (pre) {
                    int lr = lr0 + i * 16;
                    int lc = lc0 + j * 8;
                    r0v = *(const float2*)(sm_raw + STAGE128 + lr * RES_ROWB + lc * 4);
                    r1v = *(const float2*)(sm_raw + STAGE128 + (lr + 8) * RES_ROWB + lc * 4);
                } else {
                    r0v = *(const float2*)(res + (size_t)row * N + col);
                    r1v = *(const float2*)(res + (size_t)(row + 8) * N + col);
                }
                v0 += r0v.x; v1 += r0v.y;
                v2 += r1v.x; v3 += r1v.y;
                *(float2*)(Co + (size_t)row * N + col) = make_float2(v0, v1);
                *(float2*)(Co + (size_t)(row + 8) * N + col) = make_float2(v2, v3);
            } else {
                if (EPI == 2) {
                    v0 = 0.5f * v0 * (1.0f + erff(v0 * 0.70710678118654752f));
                    v1 = 0.5f * v1 * (1.0f + erff(v1 * 0.70710678118654752f));
                    v2 = 0.5f * v2 * (1.0f + erff(v2 * 0.70710678118654752f));
                    v3 = 0.5f * v3 * (1.0f + erff(v3 * 0.70710678118654752f));
                }
                st_h2(Ch + (size_t)row * N + col, v0, v1);
                st_h2(Ch + (size_t)(row + 8) * N + col, v2, v3);
            }
        }
    }
}

// ---------------------------------------------------------------------------
// Fused prep: 4 weight transposes + LN1, one launch.
// ---------------------------------------------------------------------------
__global__ __launch_bounds__(256) void prep_all(
    const float* __restrict__ Wq, const float* __restrict__ Wo,
    const float* __restrict__ Wf, const float* __restrict__ Wp,
    __half* __restrict__ Tq, __half* __restrict__ To,
    __half* __restrict__ Tf, __half* __restrict__ Tp,
    const float* __restrict__ x, const float* __restrict__ g1,
    const float* __restrict__ beta1, __half* __restrict__ yln)
{
    int bid = blockIdx.x;
    if (bid < 12288) {
        const float* W; __half* T; int K, N, r;
        if (bid < 3072)      { W = Wq; T = Tq; K = 1024; N = 3072; r = bid; }
        else if (bid < 4096) { W = Wo; T = To; K = 1024; N = 1024; r = bid - 3072; }
        else if (bid < 8192) { W = Wf; T = Tf; K = 1024; N = 4096; r = bid - 4096; }
        else                 { W = Wp; T = Tp; K = 4096; N = 1024; r = bid - 8192; }
        int nbx = N >> 5;
        int n0 = (r % nbx) * 32, k0 = (r / nbx) * 32;

        __shared__ float t[32][33];
        int tx = threadIdx.x & 31, ty = threadIdx.x >> 5;
        #pragma unroll
        for (int i = 0; i < 4; i++) {
            int kr = ty * 4 + i;
            t[kr][tx] = W[(size_t)(k0 + kr) * N + n0 + tx];
        }
        __syncthreads();
        #pragma unroll
        for (int i = 0; i < 4; i++) {
            int nr = ty * 4 + i;
            T[(size_t)(n0 + nr) * K + k0 + tx] = __float2half(t[tx][nr]);
        }
    } else {
        __shared__ float sh[16];
        int row = bid - 12288;
        int t = threadIdx.x;
        const float4* xr = (const float4*)(x + (size_t)row * DIM);
        float4 v = xr[t];
        float s  = v.x + v.y + v.z + v.w;
        float s2 = v.x*v.x + v.y*v.y + v.z*v.z + v.w*v.w;
        #pragma unroll
        for (int o = 16; o > 0; o >>= 1) {
            s  += __shfl_xor_sync(0xffffffffu, s,  o);
            s2 += __shfl_xor_sync(0xffffffffu, s2, o);
        }
        if ((t & 31) == 0) { sh[t >> 5] = s; sh[8 + (t >> 5)] = s2; }
        __syncthreads();
        if (t < 32) {
            float a  = (t < 8) ? sh[t]     : 0.0f;
            float a2 = (t < 8) ? sh[8 + t] : 0.0f;
            #pragma unroll
            for (int o = 4; o > 0; o >>= 1) {
                a  += __shfl_xor_sync(0xffffffffu, a,  o);
                a2 += __shfl_xor_sync(0xffffffffu, a2, o);
            }
            if (t == 0) { sh[0] = a; sh[1] = a2; }
        }
        __syncthreads();
        float mean = sh[0] * (1.0f / DIM);
        float var  = sh[1] * (1.0f / DIM) - mean * mean;
        float rstd = rsqrtf(var + 1e-5f);
        float4 gg = ((const float4*)g1)[t];
        float4 bb = ((const float4*)beta1)[t];
        float o0 = (v.x - mean) * rstd * gg.x + bb.x;
        float o1 = (v.y - mean) * rstd * gg.y + bb.y;
        float o2 = (v.z - mean) * rstd * gg.z + bb.z;
        float o3 = (v.w - mean) * rstd * gg.w + bb.w;
        size_t o = (size_t)row * DIM + t * 4;
        st_h2(yln + o, o0, o1);
        st_h2(yln + o + 2, o2, o3);
    }
}

// ---------------------------------------------------------------------------
// LayerNorm -> fp16 output. One block per row, 256 threads, float4. (LN2)
// ---------------------------------------------------------------------------
__global__ __launch_bounds__(256) void ln_kernel(
    const float* __restrict__ x, const float* __restrict__ g,
    const float* __restrict__ b, __half* __restrict__ y)
{
    __shared__ float sh[16];
    int row = blockIdx.x;
    int t = threadIdx.x;
    const float4* xr = (const float4*)(x + (size_t)row * DIM);
    float4 v = xr[t];
    float s  = v.x + v.y + v.z + v.w;
    float s2 = v.x*v.x + v.y*v.y + v.z*v.z + v.w*v.w;
    #pragma unroll
    for (int o = 16; o > 0; o >>= 1) {
        s  += __shfl_xor_sync(0xffffffffu, s,  o);
        s2 += __shfl_xor_sync(0xffffffffu, s2, o);
    }
    if ((t & 31) == 0) { sh[t >> 5] = s; sh[8 + (t >> 5)] = s2; }
    __syncthreads();
    if (t < 32) {
        float a  = (t < 8) ? sh[t]     : 0.0f;
        float a2 = (t < 8) ? sh[8 + t] : 0.0f;
        #pragma unroll
        for (int o = 4; o > 0; o >>= 1) {
            a  += __shfl_xor_sync(0xffffffffu, a,  o);
            a2 += __shfl_xor_sync(0xffffffffu, a2, o);
        }
        if (t == 0) { sh[0] = a; sh[1] = a2; }
    }
    __syncthreads();
    float mean = sh[0] * (1.0f / DIM);
    float var  = sh[1] * (1.0f / DIM) - mean * mean;
    float rstd = rsqrtf(var + 1e-5f);
    float4 gg = ((const float4*)g)[t];
    float4 bb = ((const float4*)b)[t];
    float o0 = (v.x - mean) * rstd * gg.x + bb.x;
    float o1 = (v.y - mean) * rstd * gg.y + bb.y;
    float o2 = (v.z - mean) * rstd * gg.z + bb.z;
    float o3 = (v.w - mean) * rstd * gg.w + bb.w;
    size_t o = (size_t)row * DIM + t * 4;
    st_h2(y + o, o0, o1);
    st_h2(y + o + 2, o2, o3);
}

// ---------------------------------------------------------------------------
// Flash attention on fp16 mma.sync, single-precision-pass.
// CTA: 128 queries x one (b,h). 8 warps, 16 q-rows each.
// KV staged in 128-row blocks (double-buffered), two 64-row halves per iter.
// Base-2 softmax (scale folds 0.125*log2(e)); branch-free rescale.
// ---------------------------------------------------------------------------
#define AT_ROWB   144
#define AT_TILE   (128 * AT_ROWB)    // 18432 per matrix (K or V), 128 rows
#define AT_STAGE  (2 * AT_TILE)      // 36864 (K, V)
#define ATTN_SMEM (2 * AT_STAGE)     // 73728
#define SCL2 0.18033688011112042f    // 0.125 * log2(e)

__global__ __launch_bounds__(256) void attn_mma(
    const __half* __restrict__ qkv,
    __half* __restrict__ oout)
{
    extern __shared__ char sm_raw[];
    uint32_t sb = smem_u32(sm_raw);

    int tid  = threadIdx.x;
    int w    = tid >> 5;
    int lane = tid & 31;
    int qb   = (int)(gridDim.x - 1 - blockIdx.x);   // long CTAs first
    int bhid = blockIdx.y;
    int b    = bhid >> 4;
    int h    = bhid & 15;
    int q0   = qb * 128;
    const int D3 = 3 * DIM;
    size_t rowbase = (size_t)(b * SEQ) * D3 + h * 64;

    const __half* kv_srcs[2] = { qkv + rowbase + DIM, qkv + rowbase + 2 * DIM };

    auto load_kv = [&](int blk, int s) {
        #pragma unroll
        for (int it = 0; it < 8; it++) {
            int idx = it * 256 + tid;
            int mat = idx >> 10;
            int rem = idx & 1023;
            int row = rem >> 3;
            int c   = rem & 7;
            const __half* src =
                kv_srcs[mat] + (size_t)(blk * 128 + row) * D3 + c * 8;
            cp16(sb + s * AT_STAGE + mat * AT_TILE + row * AT_ROWB + c * 16, src);
        }
        CP_COMMIT();
    };

    // ---- Q into stage-1 K area + KV block 0 into stage-0, one group ----
    {
        uint32_t qbase_s = sb + AT_STAGE;
        #pragma unroll
        for (int it = 0; it < 4; it++) {
            int idx = it * 256 + tid;
            int row = idx >> 3;
            int c   = idx & 7;
            const __half* src = qkv + rowbase + (size_t)(q0 + row) * D3 + c * 8;
            cp16(qbase_s + (uint32_t)(row * AT_ROWB + c * 16), src);
        }
        #pragma unroll
        for (int it = 0; it < 8; it++) {
            int idx = it * 256 + tid;
            int mat = idx >> 10;
            int rem = idx & 1023;
            int row = rem >> 3;
            int c   = rem & 7;
            const __half* src = kv_srcs[mat] + (size_t)(row) * D3 + c * 8;
            cp16(sb + mat * AT_TILE + row * AT_ROWB + c * 16, src);
        }
        CP_COMMIT();
    }
    CP_WAIT0();
    __syncthreads();

    uint32_t qf[4][4];
    {
        int row = w * 16 + (lane & 15);
        uint32_t boff = (uint32_t)(row * AT_ROWB) + (uint32_t)((lane >> 4) * 16);
        #pragma unroll
        for (int kk = 0; kk < 4; kk++)
            ldsm4(qf[kk], sb + AT_STAGE + boff + kk * 32);
    }
    __syncthreads();

    float m2[2] = { -1e30f, -1e30f };
    float l2[2] = { 0.0f, 0.0f };
    float oacc[8][4];
    #pragma unroll
    for (int j = 0; j < 8; j++)
        #pragma unroll
        for (int q = 0; q < 4; q++) oacc[j][q] = 0.0f;

    int nblk = qb + 1;
    int qrow0 = q0 + w * 16 + (lane >> 2);

    for (int blk = 0; blk < nblk; blk++) {
        int s = blk & 1;
        if (blk + 1 < nblk) { load_kv(blk + 1, s ^ 1); CP_WAIT1(); }
        else                { CP_WAIT0(); }
        __syncthreads();

        #pragma unroll
        for (int half = 0; half < 2; half++) {
            int kvbase = blk * 128 + half * 64;
            bool active = (kvbase <= q0 + w * 16 + 15);
            if (!active) continue;

            uint32_t kb_s = sb + s * AT_STAGE + (uint32_t)(half * 64 * AT_ROWB);
            uint32_t vb_s = kb_s + AT_TILE;

            float sacc[8][4];
            #pragma unroll
            for (int j = 0; j < 8; j++)
                #pragma unroll
                for (int q = 0; q < 4; q++) sacc[j][q] = 0.0f;

            int bm   = lane >> 3;
            int bkh  = bm & 1;
            int bjj  = bm >> 1;
            int brow = (lane & 7) + bjj * 8;
            #pragma unroll
            for (int jp = 0; jp < 4; jp++) {
                #pragma unroll
                for (int kk = 0; kk < 4; kk++) {
                    uint32_t off = (uint32_t)((jp * 16 + brow) * AT_ROWB)
                                 + (uint32_t)((bkh * 8 + kk * 16) * 2);
                    uint32_t khr[4];
                    ldsm4(khr, kb_s + off);
                    mma16816(sacc[2 * jp],     qf[kk], khr[0], khr[1]);
                    mma16816(sacc[2 * jp + 1], qf[kk], khr[2], khr[3]);
                }
            }

            bool needmask = (kvbase + 63 > q0 + w * 16);
            #pragma unroll
            for (int hh = 0; hh < 2; hh++) {
                int qrow = qrow0 + hh * 8;
                #pragma unroll
                for (int j = 0; j < 8; j++) {
                    #pragma unroll
                    for (int c = 0; c < 2; c++) {
                        float v = sacc[j][2 * hh + c] * SCL2;
                        if (needmask) {
                            int kv = kvbase + j * 8 + (lane & 3) * 2 + c;
                            if (kv > qrow) v = -1e30f;
                        }
                        sacc[j][2 * hh + c] = v;
                    }
                }
                float mx = -1e30f;
                #pragma unroll
                for (int j = 0; j < 8; j++)
                    mx = fmaxf(mx, fmaxf(sacc[j][2 * hh], sacc[j][2 * hh + 1]));
                mx = fmaxf(mx, __shfl_xor_sync(0xffffffffu, mx, 1));
                mx = fmaxf(mx, __shfl_xor_sync(0xffffffffu, mx, 2));
                float mn = fmaxf(m2[hh], mx);
                float sum = 0.0f;
                #pragma unroll
                for (int j = 0; j < 8; j++) {
                    float p0 = exp2f(sacc[j][2 * hh]     - mn);
                    float p1 = exp2f(sacc[j][2 * hh + 1] - mn);
                    sacc[j][2 * hh]     = p0;
                    sacc[j][2 * hh + 1] = p1;
                    sum += p0 + p1;
                }
                sum += __shfl_xor_sync(0xffffffffu, sum, 1);
                sum += __shfl_xor_sync(0xffffffffu, sum, 2);
                float alpha = exp2f(m2[hh] - mn);
                m2[hh] = mn;
                l2[hh] = l2[hh] * alpha + sum;
                #pragma unroll
                for (int j = 0; j < 8; j++) {
                    oacc[j][2 * hh]     *= alpha;
                    oacc[j][2 * hh + 1] *= alpha;
                }
            }

            uint32_t pah[4][4];
            #pragma unroll
            for (int kk = 0; kk < 4; kk++) {
                #pragma unroll
                for (int t = 0; t < 4; t++) {
                    int j  = 2 * kk + (t >> 1);
                    int ci = (t & 1) * 2;
                    pah[kk][t] = pkcvt(sacc[j][ci], sacc[j][ci + 1]);
                }
            }

            int r   = lane & 7;
            int mm  = lane >> 3;
            #pragma unroll
            for (int jp = 0; jp < 4; jp++) {
                #pragma unroll
                for (int kk = 0; kk < 4; kk++) {
                    uint32_t off = (uint32_t)((kk * 16 + r + (mm & 1) * 8) * AT_ROWB)
                                 + (uint32_t)((jp * 16 + (mm >> 1) * 8) * 2);
                    uint32_t vhr[4];
                    ldsm4t(vhr, vb_s + off);
                    mma16816(oacc[2 * jp],     pah[kk], vhr[0], vhr[1]);
                    mma16816(oacc[2 * jp + 1], pah[kk], vhr[2], vhr[3]);
                }
            }
        }
        __syncthreads();
    }

    float inv0 = 1.0f / l2[0];
    float inv1 = 1.0f / l2[1];
    size_t obase = (size_t)(b * SEQ) * DIM + h * 64;
    int row1 = q0 + w * 16 + (lane >> 2);
    int colb = (lane & 3) * 2;
    #pragma unroll
    for (int j = 0; j < 8; j++) {
        int col = j * 8 + colb;
        st_h2(oout + obase + (size_t)row1 * DIM + col,
              oacc[j][0] * inv0, oacc[j][1] * inv0);
        st_h2(oout + obase + (size_t)(row1 + 8) * DIM + col,
              oacc[j][2] * inv1, oacc[j][3] * inv1);
    }
}

// ---------------------------------------------------------------------------
// Launch
// ---------------------------------------------------------------------------
extern "C" void kernel_launch(void* const* d_in, const int* in_sizes, int n_in,
                              void* d_out, int out_size)
{
    const float* x      = (const float*)d_in[0];
    const float* W_qkv  = (const float*)d_in[1];
    const float* b_qkv  = (const float*)d_in[2];
    const float* W_o    = (const float*)d_in[3];
    const float* b_o    = (const float*)d_in[4];
    const float* W_fc   = (const float*)d_in[5];
    const float* b_fc   = (const float*)d_in[6];
    const float* W_pr   = (const float*)d_in[7];
    const float* b_pr   = (const float*)d_in[8];
    const float* g1     = (const float*)d_in[9];
    const float* beta1  = (const float*)d_in[10];
    const float* g2     = (const float*)d_in[11];
    const float* beta2  = (const float*)d_in[12];
    float* out = (float*)d_out;

    __half *pWq, *pWo, *pWf, *pWp;
    __half *ph, *pq, *pat, *ph2, *pfc;
    float *px1;
    cudaGetSymbolAddress((void**)&pWq,  g_Wqkv);
    cudaGetSymbolAddress((void**)&pWo,  g_Wo);
    cudaGetSymbolAddress((void**)&pWf,  g_Wfc);
    cudaGetSymbolAddress((void**)&pWp,  g_Wpr);
    cudaGetSymbolAddress((void**)&ph,   g_h);
    cudaGetSymbolAddress((void**)&pq,   g_qkv);
    cudaGetSymbolAddress((void**)&pat,  g_att);
    cudaGetSymbolAddress((void**)&px1,  g_x1);
    cudaGetSymbolAddress((void**)&ph2,  g_h2);
    cudaGetSymbolAddress((void**)&pfc,  g_fc);

    cudaFuncSetAttribute(attn_mma,
                         cudaFuncAttributeMaxDynamicSharedMemorySize, ATTN_SMEM);
    cudaFuncSetAttribute(gemm128<1>,
                         cudaFuncAttributeMaxDynamicSharedMemorySize, GEMM128_SMEM);
    cudaFuncSetAttribute(gemm128<2>,
                         cudaFuncAttributeMaxDynamicSharedMemorySize, GEMM128_SMEM);
    cudaFuncSetAttribute(gemm128<3>,
                         cudaFuncAttributeMaxDynamicSharedMemorySize, GEMM128_SMEM);

    // 0. Fused prep: weight transposes + LN1, one launch
    prep_all<<<16384, 256>>>(W_qkv, W_o, W_fc, W_pr, pWq, pWo, pWf, pWp,
                             x, g1, beta1, ph);
    // 2. QKV projection -> fp16
    gemm128<3><<<dim3(3072 / 128, MROWS / 128), 256, GEMM128_SMEM>>>(
        ph, pWq, b_qkv, nullptr, nullptr, pq, MROWS, 3 * DIM, DIM);
    // 3. Attention (tensor-core flash) -> att fp16
    attn_mma<<<dim3(SEQ / 128, BATCH * NHEAD), 256, ATTN_SMEM>>>(pq, pat);
    // 4. Output projection + residual -> x1 (fp32)
    gemm128<1><<<dim3(DIM / 128, MROWS / 128), 256, GEMM128_SMEM>>>(
        pat, pWo, b_o, x, px1, nullptr, MROWS, DIM, DIM);
    // 5. LN2 -> h2 (fp16)
    ln_kernel<<<MROWS, 256>>>(px1, g2, beta2, ph2);
    // 6. FC + GELU -> fc (fp16)
    gemm128<2><<<dim3(4 * DIM / 128, MROWS / 128), 256, GEMM128_SMEM>>>(
        ph2, pWf, b_fc, nullptr, nullptr, pfc, MROWS, 4 * DIM, DIM);
    // 7. Projection + residual -> out (fp32)
    gemm128<1><<<dim3(DIM / 128, MROWS / 128), 256, GEMM128_SMEM>>>(
        pfc, pWp, b_pr, px1, out, nullptr, MROWS, DIM, 4 * DIM);
}

// round 17
// speedup vs baseline: 1.0857x; 1.0674x over previous
#include <cuda_runtime.h>
#include <cuda_fp16.h>
#include <math.h>
#include <stdint.h>
#include <string.h>

// Problem constants
#define BATCH 2
#define SEQ   2048
#define DIM   1024
#define NHEAD 16
#define HDIM  64
#define MROWS (BATCH * SEQ)   // 4096

// ---------------------------------------------------------------------------
// Scratch (no allocations allowed -> __device__ globals)
// ---------------------------------------------------------------------------
__device__ __half g_Wqkv[3072 * 1024];
__device__ __half g_Wo  [1024 * 1024];
__device__ __half g_Wfc [4096 * 1024];
__device__ __half g_Wpr [1024 * 4096];

__device__ __half g_h  [MROWS * DIM];
__device__ __half g_qkv[MROWS * 3 * DIM];
__device__ __half g_att[MROWS * DIM];
__device__ float  g_x1 [MROWS * DIM];
__device__ __half g_h2 [MROWS * DIM];
__device__ __half g_fc [MROWS * 4 * DIM];

// ---------------------------------------------------------------------------
// PTX helpers (family-common only: cp.async, ldmatrix, mma.sync)
// ---------------------------------------------------------------------------
__device__ __forceinline__ uint32_t smem_u32(const void* p) {
    uint32_t a;
    asm("{ .reg .u64 t; cvta.to.shared.u64 t, %1; cvt.u32.u64 %0, t; }"
        : "=r"(a) : "l"(p));
    return a;
}

__device__ __forceinline__ void cp16(uint32_t dst, const void* src) {
    asm volatile("cp.async.cg.shared.global [%0], [%1], 16;"
                 :: "r"(dst), "l"(src));
}
#define CP_COMMIT() asm volatile("cp.async.commit_group;" ::: "memory")
#define CP_WAIT1()  asm volatile("cp.async.wait_group 1;" ::: "memory")
#define CP_WAIT0()  asm volatile("cp.async.wait_group 0;" ::: "memory")

__device__ __forceinline__ void ldsm4(uint32_t* r, uint32_t a) {
    asm volatile("ldmatrix.sync.aligned.m8n8.x4.shared.b16 {%0,%1,%2,%3}, [%4];"
                 : "=r"(r[0]), "=r"(r[1]), "=r"(r[2]), "=r"(r[3]) : "r"(a));
}
__device__ __forceinline__ void ldsm4t(uint32_t* r, uint32_t a) {
    asm volatile("ldmatrix.sync.aligned.m8n8.x4.trans.shared.b16 {%0,%1,%2,%3}, [%4];"
                 : "=r"(r[0]), "=r"(r[1]), "=r"(r[2]), "=r"(r[3]) : "r"(a));
}

__device__ __forceinline__ void mma16816(float* d, const uint32_t* a,
                                         uint32_t b0, uint32_t b1) {
    asm volatile(
        "mma.sync.aligned.m16n8k16.row.col.f32.f16.f16.f32 "
        "{%0,%1,%2,%3}, {%4,%5,%6,%7}, {%8,%9}, {%0,%1,%2,%3};"
        : "+f"(d[0]), "+f"(d[1]), "+f"(d[2]), "+f"(d[3])
        : "r"(a[0]), "r"(a[1]), "r"(a[2]), "r"(a[3]), "r"(b0), "r"(b1));
}

// single-instruction packed fp32->fp16x2 convert (cvt.rn.f16x2.f32)
__device__ __forceinline__ uint32_t pkcvt(float a, float b) {
    __half2 t = __floats2half2_rn(a, b);
    uint32_t r;
    memcpy(&r, &t, 4);
    return r;
}
__device__ __forceinline__ void st_h2(__half* p, float a, float b) {
    *(__half2*)p = __floats2half2_rn(a, b);
}

// ---------------------------------------------------------------------------
// fp16 mma.sync GEMM, single pass, BN=128, 2 CTAs/SM.
// A fp16 [M,K] K-major, B fp16 [N,K] K-major.
// Block tile 128x128, K-chunk 64, 8 warps (4x2), warp tile 32x64.
// 3-stage cp.async, ONE __syncthreads per chunk.
// Loads for chunk c+2 are issued AFTER compute of chunk c so the chunk-c
// LDSMs are not queued behind the cp.async burst in the L1tex FIFO.
// EPI=1: res tile prefetched into free smem stages during the last K-chunk.
// EPI: 1 = +bias+res -> fp32; 2 = gelu(+bias) -> fp16; 3 = +bias -> fp16
// ---------------------------------------------------------------------------
#define TS 72                        // smem row stride in fp16 elems (144 bytes)
#define ROWB (TS * 2)                // 144
#define TILE_B128 (128 * ROWB)       // 18432
#define STAGE128  (2 * TILE_B128)    // 36864
#define GEMM128_SMEM (3 * STAGE128)  // 110592
#define RES_ROWB 528                 // res smem row stride (bytes)

template <int EPI>
__global__ __launch_bounds__(256, 2) void gemm128(
    const __half* __restrict__ A, const __half* __restrict__ B,
    const float* __restrict__ bias, const float* __restrict__ res,
    float* __restrict__ Co, __half* __restrict__ Ch,
    int M, int N, int K)
{
    extern __shared__ char sm_raw[];
    uint32_t sb = smem_u32(sm_raw);

    int tid  = threadIdx.x;
    int w    = tid >> 5;
    int lane = tid & 31;
    int wm   = w >> 1;               // 0..3  (32-row group)
    int wn   = w & 1;                // 0..1  (64-col group)
    int n0   = blockIdx.x * 128;
    int m0   = blockIdx.y * 128;

    const __half* srcA = A + (size_t)m0 * K;
    const __half* srcB = B + (size_t)n0 * K;

    float acc[2][8][4];
    #pragma unroll
    for (int i = 0; i < 2; i++)
        #pragma unroll
        for (int j = 0; j < 8; j++)
            #pragma unroll
            for (int q = 0; q < 4; q++) acc[i][j][q] = 0.0f;

    int nch = K >> 6;                // K/64
    bool pre = (EPI == 1) && (((nch - 1) % 3) == 0);

    auto load_stage = [&](int c, int s) {
        int k0 = c << 6;
        uint32_t stg = sb + s * STAGE128;
        #pragma unroll
        for (int it = 0; it < 8; it++) {
            int idx = it * 256 + tid;          // 0..2047
            int mat   = idx >> 10;             // 0: A, 1: B
            int rem   = idx & 1023;
            int row   = rem >> 3;
            int chunk = rem & 7;
            const __half* src = (mat ? srcB : srcA) + (size_t)row * K + k0 + chunk * 8;
            uint32_t dst = stg + mat * TILE_B128
                         + (uint32_t)(row * ROWB + chunk * 16);
            cp16(dst, src);
        }
        CP_COMMIT();
    };

    load_stage(0, 0);
    if (nch > 1) load_stage(1, 1);

    int arow = wm * 32 + (lane & 15);
    uint32_t a_off = (uint32_t)(arow * ROWB) + (uint32_t)((lane >> 4) * 16);
    int bmat = lane >> 3;
    int b_h  = bmat & 1;
    int b_j  = bmat >> 1;
    uint32_t b_off = (uint32_t)((wn * 64 + b_j * 8 + (lane & 7)) * ROWB)
                   + (uint32_t)(b_h * 16);

    for (int c = 0; c < nch; c++) {
        int s = c % 3;
        if (c + 1 < nch) { CP_WAIT1(); } else { CP_WAIT0(); }
        __syncthreads();

        uint32_t stg = sb + s * STAGE128;
        uint32_t pA = stg;
        uint32_t pB = stg + TILE_B128;

        #pragma unroll
        for (int kk = 0; kk < 64; kk += 16) {
            uint32_t kb = (uint32_t)kk * 2;
            uint32_t ah[2][4];
            #pragma unroll
            for (int i = 0; i < 2; i++)
                ldsm4(ah[i], pA + a_off + kb + (uint32_t)(i * 16 * ROWB));
            #pragma unroll
            for (int g = 0; g < 4; g++) {
                uint32_t boff = b_off + (uint32_t)(g * 16 * ROWB) + kb;
                uint32_t bh[4];
                ldsm4(bh, pB + boff);
                int j0 = 2 * g, j1 = 2 * g + 1;
                #pragma unroll
                for (int i = 0; i < 2; i++) {
                    mma16816(acc[i][j0], ah[i], bh[0], bh[1]);
                    mma16816(acc[i][j1], ah[i], bh[2], bh[3]);
                }
            }
        }

        // issue next-next chunk's loads after this chunk's LDSMs are queued
        if (c + 2 < nch) load_stage(c + 2, (c + 2) % 3);
        else if (pre && c == nch - 1) {
            const float* rbase = res + (size_t)m0 * N + n0;
            uint32_t rdst = sb + STAGE128;
            #pragma unroll
            for (int it = 0; it < 16; it++) {
                int idx = it * 256 + tid;      // 0..4095
                int row = idx >> 5;
                int ch  = idx & 31;
                cp16(rdst + (uint32_t)(row * RES_ROWB + ch * 16),
                     rbase + (size_t)row * N + ch * 4);
            }
            CP_COMMIT();
        }
    }

    if (pre) { CP_WAIT0(); __syncthreads(); }

    // Epilogue
    int r0 = m0 + wm * 32 + (lane >> 2);
    int c0 = n0 + wn * 64 + (lane & 3) * 2;
    int lr0 = wm * 32 + (lane >> 2);
    int lc0 = wn * 64 + (lane & 3) * 2;
    #pragma unroll
    for (int i = 0; i < 2; i++) {
        int row = r0 + i * 16;
        #pragma unroll
        for (int j = 0; j < 8; j++) {
            int col = c0 + j * 8;
            float b0 = bias[col], b1 = bias[col + 1];
            float v0 = acc[i][j][0] + b0;
            float v1 = acc[i][j][1] + b1;
            float v2 = acc[i][j][2] + b0;
            float v3 = acc[i][j][3] + b1;
            if (EPI == 1) {
                float2 r0v, r1v;
                if (pre) {
                    int lr = lr0 + i * 16;
                    int lc = lc0 + j * 8;
                    r0v = *(const float2*)(sm_raw + STAGE128 + lr * RES_ROWB + lc * 4);
                    r1v = *(const float2*)(sm_raw + STAGE128 + (lr + 8) * RES_ROWB + lc * 4);
                } else {
                    r0v = *(const float2*)(res + (size_t)row * N + col);
                    r1v = *(const float2*)(res + (size_t)(row + 8) * N + col);
                }
                v0 += r0v.x; v1 += r0v.y;
                v2 += r1v.x; v3 += r1v.y;
                *(float2*)(Co + (size_t)row * N + col) = make_float2(v0, v1);
                *(float2*)(Co + (size_t)(row + 8) * N + col) = make_float2(v2, v3);
            } else {
                if (EPI == 2) {
                    v0 = 0.5f * v0 * (1.0f + erff(v0 * 0.70710678118654752f));
                    v1 = 0.5f * v1 * (1.0f + erff(v1 * 0.70710678118654752f));
                    v2 = 0.5f * v2 * (1.0f + erff(v2 * 0.70710678118654752f));
                    v3 = 0.5f * v3 * (1.0f + erff(v3 * 0.70710678118654752f));
                }
                st_h2(Ch + (size_t)row * N + col, v0, v1);
                st_h2(Ch + (size_t)(row + 8) * N + col, v2, v3);
            }
        }
    }
}

// ---------------------------------------------------------------------------
// Fused prep: 4 weight transposes + LN1, one launch.
// ---------------------------------------------------------------------------
__global__ __launch_bounds__(256) void prep_all(
    const float* __restrict__ Wq, const float* __restrict__ Wo,
    const float* __restrict__ Wf, const float* __restrict__ Wp,
    __half* __restrict__ Tq, __half* __restrict__ To,
    __half* __restrict__ Tf, __half* __restrict__ Tp,
    const float* __restrict__ x, const float* __restrict__ g1,
    const float* __restrict__ beta1, __half* __restrict__ yln)
{
    int bid = blockIdx.x;
    if (bid < 12288) {
        const float* W; __half* T; int K, N, r;
        if (bid < 3072)      { W = Wq; T = Tq; K = 1024; N = 3072; r = bid; }
        else if (bid < 4096) { W = Wo; T = To; K = 1024; N = 1024; r = bid - 3072; }
        else if (bid < 8192) { W = Wf; T = Tf; K = 1024; N = 4096; r = bid - 4096; }
        else                 { W = Wp; T = Tp; K = 4096; N = 1024; r = bid - 8192; }
        int nbx = N >> 5;
        int n0 = (r % nbx) * 32, k0 = (r / nbx) * 32;

        __shared__ float t[32][33];
        int tx = threadIdx.x & 31, ty = threadIdx.x >> 5;
        #pragma unroll
        for (int i = 0; i < 4; i++) {
            int kr = ty * 4 + i;
            t[kr][tx] = W[(size_t)(k0 + kr) * N + n0 + tx];
        }
        __syncthreads();
        #pragma unroll
        for (int i = 0; i < 4; i++) {
            int nr = ty * 4 + i;
            T[(size_t)(n0 + nr) * K + k0 + tx] = __float2half(t[tx][nr]);
        }
    } else {
        __shared__ float sh[16];
        int row = bid - 12288;
        int t = threadIdx.x;
        const float4* xr = (const float4*)(x + (size_t)row * DIM);
        float4 v = xr[t];
        float s  = v.x + v.y + v.z + v.w;
        float s2 = v.x*v.x + v.y*v.y + v.z*v.z + v.w*v.w;
        #pragma unroll
        for (int o = 16; o > 0; o >>= 1) {
            s  += __shfl_xor_sync(0xffffffffu, s,  o);
            s2 += __shfl_xor_sync(0xffffffffu, s2, o);
        }
        if ((t & 31) == 0) { sh[t >> 5] = s; sh[8 + (t >> 5)] = s2; }
        __syncthreads();
        if (t < 32) {
            float a  = (t < 8) ? sh[t]     : 0.0f;
            float a2 = (t < 8) ? sh[8 + t] : 0.0f;
            #pragma unroll
            for (int o = 4; o > 0; o >>= 1) {
                a  += __shfl_xor_sync(0xffffffffu, a,  o);
                a2 += __shfl_xor_sync(0xffffffffu, a2, o);
            }
            if (t == 0) { sh[0] = a; sh[1] = a2; }
        }
        __syncthreads();
        float mean = sh[0] * (1.0f / DIM);
        float var  = sh[1] * (1.0f / DIM) - mean * mean;
        float rstd = rsqrtf(var + 1e-5f);
        float4 gg = ((const float4*)g1)[t];
        float4 bb = ((const float4*)beta1)[t];
        float o0 = (v.x - mean) * rstd * gg.x + bb.x;
        float o1 = (v.y - mean) * rstd * gg.y + bb.y;
        float o2 = (v.z - mean) * rstd * gg.z + bb.z;
        float o3 = (v.w - mean) * rstd * gg.w + bb.w;
        size_t o = (size_t)row * DIM + t * 4;
        st_h2(yln + o, o0, o1);
        st_h2(yln + o + 2, o2, o3);
    }
}

// ---------------------------------------------------------------------------
// LayerNorm -> fp16 output. One block per row, 256 threads, float4. (LN2)
// ---------------------------------------------------------------------------
__global__ __launch_bounds__(256) void ln_kernel(
    const float* __restrict__ x, const float* __restrict__ g,
    const float* __restrict__ b, __half* __restrict__ y)
{
    __shared__ float sh[16];
    int row = blockIdx.x;
    int t = threadIdx.x;
    const float4* xr = (const float4*)(x + (size_t)row * DIM);
    float4 v = xr[t];
    float s  = v.x + v.y + v.z + v.w;
    float s2 = v.x*v.x + v.y*v.y + v.z*v.z + v.w*v.w;
    #pragma unroll
    for (int o = 16; o > 0; o >>= 1) {
        s  += __shfl_xor_sync(0xffffffffu, s,  o);
        s2 += __shfl_xor_sync(0xffffffffu, s2, o);
    }
    if ((t & 31) == 0) { sh[t >> 5] = s; sh[8 + (t >> 5)] = s2; }
    __syncthreads();
    if (t < 32) {
        float a  = (t < 8) ? sh[t]     : 0.0f;
        float a2 = (t < 8) ? sh[8 + t] : 0.0f;
        #pragma unroll
        for (int o = 4; o > 0; o >>= 1) {
            a  += __shfl_xor_sync(0xffffffffu, a,  o);
            a2 += __shfl_xor_sync(0xffffffffu, a2, o);
        }
        if (t == 0) { sh[0] = a; sh[1] = a2; }
    }
    __syncthreads();
    float mean = sh[0] * (1.0f / DIM);
    float var  = sh[1] * (1.0f / DIM) - mean * mean;
    float rstd = rsqrtf(var + 1e-5f);
    float4 gg = ((const float4*)g)[t];
    float4 bb = ((const float4*)b)[t];
    float o0 = (v.x - mean) * rstd * gg.x + bb.x;
    float o1 = (v.y - mean) * rstd * gg.y + bb.y;
    float o2 = (v.z - mean) * rstd * gg.z + bb.z;
    float o3 = (v.w - mean) * rstd * gg.w + bb.w;
    size_t o = (size_t)row * DIM + t * 4;
    st_h2(y + o, o0, o1);
    st_h2(y + o + 2, o2, o3);
}

// ---------------------------------------------------------------------------
// Flash attention on fp16 mma.sync, single-precision-pass.
// CTA: 128 queries x one (b,h). 8 warps, 16 q-rows each.
// KV staged in 128-row blocks (double-buffered), two 64-row halves per iter.
// Base-2 softmax (scale folds 0.125*log2(e)); branch-free rescale.
// ---------------------------------------------------------------------------
#define AT_ROWB   144
#define AT_TILE   (128 * AT_ROWB)    // 18432 per matrix (K or V), 128 rows
#define AT_STAGE  (2 * AT_TILE)      // 36864 (K, V)
#define ATTN_SMEM (2 * AT_STAGE)     // 73728
#define SCL2 0.18033688011112042f    // 0.125 * log2(e)

__global__ __launch_bounds__(256) void attn_mma(
    const __half* __restrict__ qkv,
    __half* __restrict__ oout)
{
    extern __shared__ char sm_raw[];
    uint32_t sb = smem_u32(sm_raw);

    int tid  = threadIdx.x;
    int w    = tid >> 5;
    int lane = tid & 31;
    int qb   = (int)(gridDim.x - 1 - blockIdx.x);   // long CTAs first
    int bhid = blockIdx.y;
    int b    = bhid >> 4;
    int h    = bhid & 15;
    int q0   = qb * 128;
    const int D3 = 3 * DIM;
    size_t rowbase = (size_t)(b * SEQ) * D3 + h * 64;

    const __half* kv_srcs[2] = { qkv + rowbase + DIM, qkv + rowbase + 2 * DIM };

    auto load_kv = [&](int blk, int s) {
        #pragma unroll
        for (int it = 0; it < 8; it++) {
            int idx = it * 256 + tid;
            int mat = idx >> 10;
            int rem = idx & 1023;
            int row = rem >> 3;
            int c   = rem & 7;
            const __half* src =
                kv_srcs[mat] + (size_t)(blk * 128 + row) * D3 + c * 8;
            cp16(sb + s * AT_STAGE + mat * AT_TILE + row * AT_ROWB + c * 16, src);
        }
        CP_COMMIT();
    };

    // ---- Q into stage-1 K area + KV block 0 into stage-0, one group ----
    {
        uint32_t qbase_s = sb + AT_STAGE;
        #pragma unroll
        for (int it = 0; it < 4; it++) {
            int idx = it * 256 + tid;
            int row = idx >> 3;
            int c   = idx & 7;
            const __half* src = qkv + rowbase + (size_t)(q0 + row) * D3 + c * 8;
            cp16(qbase_s + (uint32_t)(row * AT_ROWB + c * 16), src);
        }
        #pragma unroll
        for (int it = 0; it < 8; it++) {
            int idx = it * 256 + tid;
            int mat = idx >> 10;
            int rem = idx & 1023;
            int row = rem >> 3;
            int c   = rem & 7;
            const __half* src = kv_srcs[mat] + (size_t)(row) * D3 + c * 8;
            cp16(sb + mat * AT_TILE + row * AT_ROWB + c * 16, src);
        }
        CP_COMMIT();
    }
    CP_WAIT0();
    __syncthreads();

    uint32_t qf[4][4];
    {
        int row = w * 16 + (lane & 15);
        uint32_t boff = (uint32_t)(row * AT_ROWB) + (uint32_t)((lane >> 4) * 16);
        #pragma unroll
        for (int kk = 0; kk < 4; kk++)
            ldsm4(qf[kk], sb + AT_STAGE + boff + kk * 32);
    }
    __syncthreads();

    float m2[2] = { -1e30f, -1e30f };
    float l2[2] = { 0.0f, 0.0f };
    float oacc[8][4];
    #pragma unroll
    for (int j = 0; j < 8; j++)
        #pragma unroll
        for (int q = 0; q < 4; q++) oacc[j][q] = 0.0f;

    int nblk = qb + 1;
    int qrow0 = q0 + w * 16 + (lane >> 2);

    for (int blk = 0; blk < nblk; blk++) {
        int s = blk & 1;
        if (blk + 1 < nblk) { load_kv(blk + 1, s ^ 1); CP_WAIT1(); }
        else                { CP_WAIT0(); }
        __syncthreads();

        #pragma unroll
        for (int half = 0; half < 2; half++) {
            int kvbase = blk * 128 + half * 64;
            bool active = (kvbase <= q0 + w * 16 + 15);
            if (!active) continue;

            uint32_t kb_s = sb + s * AT_STAGE + (uint32_t)(half * 64 * AT_ROWB);
            uint32_t vb_s = kb_s + AT_TILE;

            float sacc[8][4];
            #pragma unroll
            for (int j = 0; j < 8; j++)
                #pragma unroll
                for (int q = 0; q < 4; q++) sacc[j][q] = 0.0f;

            int bm   = lane >> 3;
            int bkh  = bm & 1;
            int bjj  = bm >> 1;
            int brow = (lane & 7) + bjj * 8;
            #pragma unroll
            for (int jp = 0; jp < 4; jp++) {
                #pragma unroll
                for (int kk = 0; kk < 4; kk++) {
                    uint32_t off = (uint32_t)((jp * 16 + brow) * AT_ROWB)
                                 + (uint32_t)((bkh * 8 + kk * 16) * 2);
                    uint32_t khr[4];
                    ldsm4(khr, kb_s + off);
                    mma16816(sacc[2 * jp],     qf[kk], khr[0], khr[1]);
                    mma16816(sacc[2 * jp + 1], qf[kk], khr[2], khr[3]);
                }
            }

            bool needmask = (kvbase + 63 > q0 + w * 16);
            #pragma unroll
            for (int hh = 0; hh < 2; hh++) {
                int qrow = qrow0 + hh * 8;
                #pragma unroll
                for (int j = 0; j < 8; j++) {
                    #pragma unroll
                    for (int c = 0; c < 2; c++) {
                        float v = sacc[j][2 * hh + c] * SCL2;
                        if (needmask) {
                            int kv = kvbase + j * 8 + (lane & 3) * 2 + c;
                            if (kv > qrow) v = -1e30f;
                        }
                        sacc[j][2 * hh + c] = v;
                    }
                }
                float mx = -1e30f;
                #pragma unroll
                for (int j = 0; j < 8; j++)
                    mx = fmaxf(mx, fmaxf(sacc[j][2 * hh], sacc[j][2 * hh + 1]));
                mx = fmaxf(mx, __shfl_xor_sync(0xffffffffu, mx, 1));
                mx = fmaxf(mx, __shfl_xor_sync(0xffffffffu, mx, 2));
                float mn = fmaxf(m2[hh], mx);
                float sum = 0.0f;
                #pragma unroll
                for (int j = 0; j < 8; j++) {
                    float p0 = exp2f(sacc[j][2 * hh]     - mn);
                    float p1 = exp2f(sacc[j][2 * hh + 1] - mn);
                    sacc[j][2 * hh]     = p0;
                    sacc[j][2 * hh + 1] = p1;
                    sum += p0 + p1;
                }
                sum += __shfl_xor_sync(0xffffffffu, sum, 1);
                sum += __shfl_xor_sync(0xffffffffu, sum, 2);
                float alpha = exp2f(m2[hh] - mn);
                m2[hh] = mn;
                l2[hh] = l2[hh] * alpha + sum;
                #pragma unroll
                for (int j = 0; j < 8; j++) {
                    oacc[j][2 * hh]     *= alpha;
                    oacc[j][2 * hh + 1] *= alpha;
                }
            }

            uint32_t pah[4][4];
            #pragma unroll
            for (int kk = 0; kk < 4; kk++) {
                #pragma unroll
                for (int t = 0; t < 4; t++) {
                    int j  = 2 * kk + (t >> 1);
                    int ci = (t & 1) * 2;
                    pah[kk][t] = pkcvt(sacc[j][ci], sacc[j][ci + 1]);
                }
            }

            int r   = lane & 7;
            int mm  = lane >> 3;
            #pragma unroll
            for (int jp = 0; jp < 4; jp++) {
                #pragma unroll
                for (int kk = 0; kk < 4; kk++) {
                    uint32_t off = (uint32_t)((kk * 16 + r + (mm & 1) * 8) * AT_ROWB)
                                 + (uint32_t)((jp * 16 + (mm >> 1) * 8) * 2);
                    uint32_t vhr[4];
                    ldsm4t(vhr, vb_s + off);
                    mma16816(oacc[2 * jp],     pah[kk], vhr[0], vhr[1]);
                    mma16816(oacc[2 * jp + 1], pah[kk], vhr[2], vhr[3]);
                }
            }
        }
        __syncthreads();
    }

    float inv0 = 1.0f / l2[0];
    float inv1 = 1.0f / l2[1];
    size_t obase = (size_t)(b * SEQ) * DIM + h * 64;
    int row1 = q0 + w * 16 + (lane >> 2);
    int colb = (lane & 3) * 2;
    #pragma unroll
    for (int j = 0; j < 8; j++) {
        int col = j * 8 + colb;
        st_h2(oout + obase + (size_t)row1 * DIM + col,
              oacc[j][0] * inv0, oacc[j][1] * inv0);
        st_h2(oout + obase + (size_t)(row1 + 8) * DIM + col,
              oacc[j][2] * inv1, oacc[j][3] * inv1);
    }
}

// ---------------------------------------------------------------------------
// Launch
// ---------------------------------------------------------------------------
extern "C" void kernel_launch(void* const* d_in, const int* in_sizes, int n_in,
                              void* d_out, int out_size)
{
    const float* x      = (const float*)d_in[0];
    const float* W_qkv  = (const float*)d_in[1];
    const float* b_qkv  = (const float*)d_in[2];
    const float* W_o    = (const float*)d_in[3];
    const float* b_o    = (const float*)d_in[4];
    const float* W_fc   = (const float*)d_in[5];
    const float* b_fc   = (const float*)d_in[6];
    const float* W_pr   = (const float*)d_in[7];
    const float* b_pr   = (const float*)d_in[8];
    const float* g1     = (const float*)d_in[9];
    const float* beta1  = (const float*)d_in[10];
    const float* g2     = (const float*)d_in[11];
    const float* beta2  = (const float*)d_in[12];
    float* out = (float*)d_out;

    __half *pWq, *pWo, *pWf, *pWp;
    __half *ph, *pq, *pat, *ph2, *pfc;
    float *px1;
    cudaGetSymbolAddress((void**)&pWq,  g_Wqkv);
    cudaGetSymbolAddress((void**)&pWo,  g_Wo);
    cudaGetSymbolAddress((void**)&pWf,  g_Wfc);
    cudaGetSymbolAddress((void**)&pWp,  g_Wpr);
    cudaGetSymbolAddress((void**)&ph,   g_h);
    cudaGetSymbolAddress((void**)&pq,   g_qkv);
    cudaGetSymbolAddress((void**)&pat,  g_att);
    cudaGetSymbolAddress((void**)&px1,  g_x1);
    cudaGetSymbolAddress((void**)&ph2,  g_h2);
    cudaGetSymbolAddress((void**)&pfc,  g_fc);

    cudaFuncSetAttribute(attn_mma,
                         cudaFuncAttributeMaxDynamicSharedMemorySize, ATTN_SMEM);
    cudaFuncSetAttribute(gemm128<1>,
                         cudaFuncAttributeMaxDynamicSharedMemorySize, GEMM128_SMEM);
    cudaFuncSetAttribute(gemm128<2>,
                         cudaFuncAttributeMaxDynamicSharedMemorySize, GEMM128_SMEM);
    cudaFuncSetAttribute(gemm128<3>,
                         cudaFuncAttributeMaxDynamicSharedMemorySize, GEMM128_SMEM);

    // 0. Fused prep: weight transposes + LN1, one launch
    prep_all<<<16384, 256>>>(W_qkv, W_o, W_fc, W_pr, pWq, pWo, pWf, pWp,
                             x, g1, beta1, ph);
    // 2. QKV projection -> fp16
    gemm128<3><<<dim3(3072 / 128, MROWS / 128), 256, GEMM128_SMEM>>>(
        ph, pWq, b_qkv, nullptr, nullptr, pq, MROWS, 3 * DIM, DIM);
    // 3. Attention (tensor-core flash) -> att fp16
    attn_mma<<<dim3(SEQ / 128, BATCH * NHEAD), 256, ATTN_SMEM>>>(pq, pat);
    // 4. Output projection + residual -> x1 (fp32)
    gemm128<1><<<dim3(DIM / 128, MROWS / 128), 256, GEMM128_SMEM>>>(
        pat, pWo, b_o, x, px1, nullptr, MROWS, DIM, DIM);
    // 5. LN2 -> h2 (fp16)
    ln_kernel<<<MROWS, 256>>>(px1, g2, beta2, ph2);
    // 6. FC + GELU -> fc (fp16)
    gemm128<2><<<dim3(4 * DIM / 128, MROWS / 128), 256, GEMM128_SMEM>>>(
        ph2, pWf, b_fc, nullptr, nullptr, pfc, MROWS, 4 * DIM, DIM);
    // 7. Projection + residual -> out (fp32)
    gemm128<1><<<dim3(DIM / 128, MROWS / 128), 256, GEMM128_SMEM>>>(
        pfc, pWp, b_pr, px1, out, nullptr, MROWS, DIM, 4 * DIM);
}